// round 1
// baseline (speedup 1.0000x reference)
#include <cuda_runtime.h>
#include <cuda_bf16.h>
#include <cstdint>

#define NSPK 2048
#define MUTT 16
#define DDIM 512
#define NROWS (NSPK*MUTT)
#define EPSC 1e-6f

#define MT 128
#define NT 128
#define KS 64
#define KSTEPS 4
#define NSLICES (DDIM/KS)
#define NCHUNKS (NSPK/NT)
#define K2_SMEM (65536 + 512)

// ---------------- scratch (device globals; no runtime allocation) ------------
__device__ __align__(256) __nv_bfloat16 g_A[NROWS*DDIM];   // normalized rows (bf16)
__device__ __align__(256) __nv_bfloat16 g_B[NSPK*DDIM];    // normalized centroids (bf16)
__device__ float g_rowsum[NROWS];
__device__ float g_simown[NROWS];
__device__ float g_simfull[NROWS];

// ---------------- K0: zero the output scalar ---------------------------------
__global__ void k0_zero(float* out) { out[0] = 0.f; }

// ---------------- K1: per-speaker prep ---------------------------------------
// computes: g_B[j]   = spk_sum / |spk_sum|       (bf16)
//           g_A[r]   = e / |e|                   (bf16)
//           g_simfull[r] = w*max(cos(e, full centroid), eps) + b
//           g_simown [r] = w*max(cos(e, LOO centroid),  eps) + b
__global__ __launch_bounds__(128) void k1_prep(const float* __restrict__ dvecs,
                                               const float* __restrict__ wp,
                                               const float* __restrict__ bp) {
    __shared__ float tile[MUTT*DDIM];
    __shared__ float ssum[DDIM];
    __shared__ float redA[4], redB[4];

    const int j = blockIdx.x, tid = threadIdx.x;
    const int lane = tid & 31, wid = tid >> 5;

    const float4* src = (const float4*)(dvecs + (size_t)j * MUTT * DDIM);
    float4* t4p = (float4*)tile;
    #pragma unroll
    for (int q = 0; q < 16; q++) t4p[tid + 128*q] = src[tid + 128*q];
    __syncthreads();

    float ssqp = 0.f;
    #pragma unroll
    for (int c = 0; c < 4; c++) {
        const int d = tid + 128*c;
        float s = 0.f;
        #pragma unroll
        for (int i = 0; i < MUTT; i++) s += tile[i*DDIM + d];
        ssum[d] = s;
        ssqp += s * s;
    }
    #pragma unroll
    for (int o = 16; o; o >>= 1) ssqp += __shfl_xor_sync(0xffffffffu, ssqp, o);
    if (lane == 0) redA[wid] = ssqp;
    __syncthreads();
    const float ssq = redA[0] + redA[1] + redA[2] + redA[3];
    const float inv_S = rsqrtf(ssq);

    #pragma unroll
    for (int c = 0; c < 4; c++) {
        const int d = tid + 128*c;
        g_B[(size_t)j*DDIM + d] = __float2bfloat16(ssum[d] * inv_S);
    }
    const float w = *wp, b = *bp;
    __syncthreads();

    for (int i = 0; i < MUTT; i++) {
        float dp = 0.f, ep = 0.f;
        #pragma unroll
        for (int c = 0; c < 4; c++) {
            const int d = tid + 128*c;
            const float v = tile[i*DDIM + d];
            dp += v * ssum[d];
            ep += v * v;
        }
        #pragma unroll
        for (int o = 16; o; o >>= 1) {
            dp += __shfl_xor_sync(0xffffffffu, dp, o);
            ep += __shfl_xor_sync(0xffffffffu, ep, o);
        }
        if (lane == 0) { redA[wid] = dp; redB[wid] = ep; }
        __syncthreads();
        const float dot_es = redA[0] + redA[1] + redA[2] + redA[3];
        const float ee     = redB[0] + redB[1] + redB[2] + redB[3];
        const float inv_e  = rsqrtf(ee);
        const int r = j * MUTT + i;
        if (tid == 0) {
            // cos vs full centroid: (e.S)/(|e||S|)
            const float cosF = dot_es * inv_e * inv_S;
            // LOO: cloo = (S - e)/(M-1); (M-1) cancels in the cosine
            const float den  = fmaxf(ssq - 2.f*dot_es + ee, 1e-20f);
            const float cosL = (dot_es - ee) * inv_e * rsqrtf(den);
            g_simfull[r] = fmaf(fmaxf(cosF, EPSC), w, b);
            g_simown[r]  = fmaf(fmaxf(cosL, EPSC), w, b);
        }
        #pragma unroll
        for (int c = 0; c < 4; c++) {
            const int d = tid + 128*c;
            g_A[(size_t)r*DDIM + d] = __float2bfloat16(tile[i*DDIM + d] * inv_e);
        }
        __syncthreads();
    }
}

// ---------------- K2: fused bf16 GEMM + exp row-sum ---------------------------
__device__ __forceinline__ void cp_ca(uint32_t d, const void* s) {
    asm volatile("cp.async.ca.shared.global [%0], [%1], 16;\n" :: "r"(d), "l"(s));
}
__device__ __forceinline__ void cp_cg(uint32_t d, const void* s) {
    asm volatile("cp.async.cg.shared.global [%0], [%1], 16;\n" :: "r"(d), "l"(s));
}
__device__ __forceinline__ void mma16816(float c[4], const uint32_t a[4], const uint32_t b[2]) {
    asm volatile("mma.sync.aligned.m16n8k16.row.col.f32.bf16.bf16.f32 "
                 "{%0,%1,%2,%3}, {%4,%5,%6,%7}, {%8,%9}, {%0,%1,%2,%3};"
                 : "+f"(c[0]), "+f"(c[1]), "+f"(c[2]), "+f"(c[3])
                 : "r"(a[0]), "r"(a[1]), "r"(a[2]), "r"(a[3]), "r"(b[0]), "r"(b[1]));
}

__global__ __launch_bounds__(256, 2) void k2_gemm(const float* __restrict__ wp,
                                                  const float* __restrict__ bp) {
    extern __shared__ unsigned char dyns[];
    uint32_t* sw = (uint32_t*)dyns;                 // 16384 words = 64KB (A0,A1,B0,B1)
    float* rowAcc = (float*)(dyns + 65536);         // 128 floats

    const int tid = threadIdx.x;
    const int rowBase = blockIdx.x * MT;
    if (tid < MT) rowAcc[tid] = 0.f;

    const int lane = tid & 31;
    const int warp = tid >> 5;
    const int wm = warp >> 2;   // 0..1  (64 rows each)
    const int wn = warp & 3;    // 0..3  (32 cols each)
    const int g  = lane >> 2;   // 0..7
    const int tt = lane & 3;    // 0..3
    const float w = *wp, b = *bp;
    __syncthreads();

    for (int nc = 0; nc < NCHUNKS; nc++) {
        float acc[4][4][4];
        #pragma unroll
        for (int x = 0; x < 4; x++)
            #pragma unroll
            for (int y = 0; y < 4; y++)
                #pragma unroll
                for (int z = 0; z < 4; z++) acc[x][y][z] = 0.f;

        // prologue: slice 0 -> buf 0
        #pragma unroll
        for (int q = 0; q < 4; q++) {
            const int c = tid + 256*q;
            const int row = c >> 3, kc = c & 7;
            const uint32_t word = (uint32_t)(row*32 + ((kc*4) ^ ((row & 7) << 2)));
            cp_ca((uint32_t)__cvta_generic_to_shared(sw + word),
                  g_A + (size_t)(rowBase + row)*DDIM + kc*8);
            cp_cg((uint32_t)__cvta_generic_to_shared(sw + 8192u + word),
                  g_B + (size_t)(nc*NT + row)*DDIM + kc*8);
        }
        asm volatile("cp.async.commit_group;\n");

        for (int ks = 0; ks < NSLICES; ks++) {
            if (ks + 1 < NSLICES) {
                const uint32_t buf = (uint32_t)((ks + 1) & 1) * 4096u;
                #pragma unroll
                for (int q = 0; q < 4; q++) {
                    const int c = tid + 256*q;
                    const int row = c >> 3, kc = c & 7;
                    const uint32_t word = buf + (uint32_t)(row*32 + ((kc*4) ^ ((row & 7) << 2)));
                    cp_ca((uint32_t)__cvta_generic_to_shared(sw + word),
                          g_A + (size_t)(rowBase + row)*DDIM + (ks+1)*KS + kc*8);
                    cp_cg((uint32_t)__cvta_generic_to_shared(sw + 8192u + word),
                          g_B + (size_t)(nc*NT + row)*DDIM + (ks+1)*KS + kc*8);
                }
                asm volatile("cp.async.commit_group;\n");
                asm volatile("cp.async.wait_group 1;\n");
            } else {
                asm volatile("cp.async.wait_group 0;\n");
            }
            __syncthreads();

            const uint32_t aB = (uint32_t)(ks & 1) * 4096u;
            const uint32_t bB = 8192u + aB;
            #pragma unroll
            for (int kk = 0; kk < KSTEPS; kk++) {
                const uint32_t kwsw = (uint32_t)((kk*8 + tt) ^ (g << 2));
                uint32_t afr[4][4], bfr[4][2];
                #pragma unroll
                for (int mt = 0; mt < 4; mt++) {
                    const int row = wm*64 + mt*16 + g;
                    const uint32_t w0 = aB + (uint32_t)(row*32) + kwsw;
                    afr[mt][0] = sw[w0];
                    afr[mt][1] = sw[w0 + 256u];
                    afr[mt][2] = sw[w0 ^ 4u];
                    afr[mt][3] = sw[(w0 + 256u) ^ 4u];
                }
                #pragma unroll
                for (int nt = 0; nt < 4; nt++) {
                    const int n = wn*32 + nt*8 + g;
                    const uint32_t wb = bB + (uint32_t)(n*32) + kwsw;
                    bfr[nt][0] = sw[wb];
                    bfr[nt][1] = sw[wb ^ 4u];
                }
                #pragma unroll
                for (int mt = 0; mt < 4; mt++)
                    #pragma unroll
                    for (int nt = 0; nt < 4; nt++)
                        mma16816(acc[mt][nt], afr[mt], bfr[nt]);
            }
            __syncthreads();
        }

        // epilogue: sim = w*max(cos,eps)+b ; accumulate exp row-wise
        #pragma unroll
        for (int mt = 0; mt < 4; mt++) {
            float s0 = 0.f, s1 = 0.f;
            #pragma unroll
            for (int nt = 0; nt < 4; nt++) {
                s0 += __expf(fmaf(fmaxf(acc[mt][nt][0], EPSC), w, b));
                s0 += __expf(fmaf(fmaxf(acc[mt][nt][1], EPSC), w, b));
                s1 += __expf(fmaf(fmaxf(acc[mt][nt][2], EPSC), w, b));
                s1 += __expf(fmaf(fmaxf(acc[mt][nt][3], EPSC), w, b));
            }
            s0 += __shfl_xor_sync(0xffffffffu, s0, 1);
            s0 += __shfl_xor_sync(0xffffffffu, s0, 2);
            s1 += __shfl_xor_sync(0xffffffffu, s1, 1);
            s1 += __shfl_xor_sync(0xffffffffu, s1, 2);
            if (tt == 0) {
                atomicAdd(&rowAcc[wm*64 + mt*16 + g],     s0);
                atomicAdd(&rowAcc[wm*64 + mt*16 + g + 8], s1);
            }
        }
        __syncthreads();
    }

    if (tid < MT) g_rowsum[rowBase + tid] = rowAcc[tid];
}

// ---------------- K3: per-row loss + global sum -------------------------------
__global__ __launch_bounds__(256) void k3_final(float* out) {
    const int r = blockIdx.x * 256 + threadIdx.x;
    const float so = g_simown[r], sf = g_simfull[r];
    float v = __logf(g_rowsum[r] - __expf(sf) + __expf(so)) - so;
    #pragma unroll
    for (int o = 16; o; o >>= 1) v += __shfl_xor_sync(0xffffffffu, v, o);
    __shared__ float sred[8];
    if ((threadIdx.x & 31) == 0) sred[threadIdx.x >> 5] = v;
    __syncthreads();
    if (threadIdx.x == 0) {
        float t = 0.f;
        #pragma unroll
        for (int i = 0; i < 8; i++) t += sred[i];
        atomicAdd(out, t);
    }
}

// ---------------- launcher ----------------------------------------------------
extern "C" void kernel_launch(void* const* d_in, const int* in_sizes, int n_in,
                              void* d_out, int out_size) {
    const float* dvecs = (const float*)d_in[0];
    const float* wp    = (const float*)d_in[1];
    const float* bp    = (const float*)d_in[2];
    float* out = (float*)d_out;

    cudaFuncSetAttribute(k2_gemm, cudaFuncAttributeMaxDynamicSharedMemorySize, K2_SMEM);

    k0_zero<<<1, 1>>>(out);
    k1_prep<<<NSPK, 128>>>(dvecs, wp, bp);
    k2_gemm<<<NROWS/MT, 256, K2_SMEM>>>(wp, bp);
    k3_final<<<NROWS/256, 256>>>(out);
}

// round 3
// speedup vs baseline: 1.2089x; 1.2089x over previous
#include <cuda_runtime.h>
#include <cuda_bf16.h>
#include <cstdint>

#define NSPK 2048
#define MUTT 16
#define DDIM 512
#define NROWS (NSPK*MUTT)
#define EPSC 1e-6f
#define LOG2E 1.4426950408889634f

// ---- k2 tiling: 128 rows/CTA, 16 col-chunks of 128, K in 4 slices of 128 fp8 ----
#define MT 128
#define NCHUNK 16
#define SLICE_B 16384           // 128 x 128 bytes
#define OFF_B   65536           // A resident: 4 slices x 16KB
#define OFF_ACC 98304
#define SMEM_K2 (OFF_ACC + 512)

// ---- scratch ----
__device__ __align__(256) uint8_t g_A8[NROWS*DDIM];   // rows * sqrt(K), e4m3
__device__ __align__(256) uint8_t g_B8[NSPK*DDIM];    // centroids * sqrt(K), e4m3
__device__ float g_rowsum[NROWS];
__device__ float g_cosF[NROWS];
__device__ float g_cosL[NROWS];

// ---------------- helpers ----------------
__device__ __forceinline__ uint32_t smem_u32(const void* p) {
    uint32_t a;
    asm("{ .reg .u64 t; cvta.to.shared.u64 t, %1; cvt.u32.u64 %0, t; }" : "=r"(a) : "l"(p));
    return a;
}
__device__ __forceinline__ void cp_cg16(uint32_t dst, const void* src) {
    asm volatile("cp.async.cg.shared.global [%0], [%1], 16;" :: "r"(dst), "l"(src));
}
__device__ __forceinline__ void ldsm4(uint32_t r[4], uint32_t addr) {
    asm volatile("ldmatrix.sync.aligned.m8n8.x4.shared.b16 {%0,%1,%2,%3}, [%4];"
                 : "=r"(r[0]), "=r"(r[1]), "=r"(r[2]), "=r"(r[3]) : "r"(addr));
}
__device__ __forceinline__ void mma_e4m3(float c[4], const uint32_t a[4], const uint32_t b[2]) {
    asm volatile("mma.sync.aligned.m16n8k32.row.col.f32.e4m3.e4m3.f32 "
                 "{%0,%1,%2,%3}, {%4,%5,%6,%7}, {%8,%9}, {%0,%1,%2,%3};"
                 : "+f"(c[0]), "+f"(c[1]), "+f"(c[2]), "+f"(c[3])
                 : "r"(a[0]), "r"(a[1]), "r"(a[2]), "r"(a[3]), "r"(b[0]), "r"(b[1]));
}
__device__ __forceinline__ float ex2f(float x) {
    float y; asm("ex2.approx.ftz.f32 %0, %1;" : "=f"(y) : "f"(x)); return y;
}
__device__ __forceinline__ uint32_t pack4_e4m3(float v0, float v1, float v2, float v3) {
    uint16_t lo, hi;
    asm("cvt.rn.satfinite.e4m3x2.f32 %0, %1, %2;" : "=h"(lo) : "f"(v1), "f"(v0));
    asm("cvt.rn.satfinite.e4m3x2.f32 %0, %1, %2;" : "=h"(hi) : "f"(v3), "f"(v2));
    return (uint32_t)lo | ((uint32_t)hi << 16);
}

// ---------------- K0 ----------------
__global__ void k0_zero(float* out) { out[0] = 0.f; }

// ---------------- K1: per-speaker prep -> fp8 scaled by sqrt(w*log2e) ----------------
__global__ __launch_bounds__(128) void k1_prep(const float* __restrict__ dvecs,
                                               const float* __restrict__ wp) {
    __shared__ float tile[MUTT*DDIM];
    __shared__ float redA[4], redB[4];

    const int j = blockIdx.x, tid = threadIdx.x;
    const int lane = tid & 31, wid = tid >> 5;
    const float w = *wp;
    const float sA = sqrtf(w * LOG2E);

    const float4* src = (const float4*)(dvecs + (size_t)j * MUTT * DDIM);
    float4* t4 = (float4*)tile;
    #pragma unroll
    for (int q = 0; q < 16; q++) t4[tid + 128*q] = src[tid + 128*q];
    __syncthreads();

    // per-thread 4 dims: 4*tid .. 4*tid+3
    float s0 = 0.f, s1 = 0.f, s2 = 0.f, s3 = 0.f;
    const float4* t4c = (const float4*)tile;
    #pragma unroll
    for (int i = 0; i < MUTT; i++) {
        const float4 v = t4c[i*128 + tid];
        s0 += v.x; s1 += v.y; s2 += v.z; s3 += v.w;
    }
    float ssqp = s0*s0 + s1*s1 + s2*s2 + s3*s3;
    #pragma unroll
    for (int o = 16; o; o >>= 1) ssqp += __shfl_xor_sync(0xffffffffu, ssqp, o);
    if (lane == 0) redA[wid] = ssqp;
    __syncthreads();
    const float ssq = redA[0] + redA[1] + redA[2] + redA[3];
    const float inv_S = rsqrtf(ssq);

    const float fB = inv_S * sA;
    ((uint32_t*)g_B8)[(size_t)j*128 + tid] = pack4_e4m3(s0*fB, s1*fB, s2*fB, s3*fB);
    __syncthreads();

    for (int i = 0; i < MUTT; i++) {
        const float4 v = t4c[i*128 + tid];
        float dp = v.x*s0 + v.y*s1 + v.z*s2 + v.w*s3;
        float ep = v.x*v.x + v.y*v.y + v.z*v.z + v.w*v.w;
        #pragma unroll
        for (int o = 16; o; o >>= 1) {
            dp += __shfl_xor_sync(0xffffffffu, dp, o);
            ep += __shfl_xor_sync(0xffffffffu, ep, o);
        }
        if (lane == 0) { redA[wid] = dp; redB[wid] = ep; }
        __syncthreads();
        const float dot_es = redA[0] + redA[1] + redA[2] + redA[3];
        const float ee     = redB[0] + redB[1] + redB[2] + redB[3];
        const float inv_e  = rsqrtf(ee);
        const int r = j * MUTT + i;
        if (tid == 0) {
            const float cosF = dot_es * inv_e * inv_S;
            const float den  = fmaxf(ssq - 2.f*dot_es + ee, 1e-20f);
            const float cosL = (dot_es - ee) * inv_e * rsqrtf(den);
            g_cosF[r] = fmaxf(cosF, EPSC);
            g_cosL[r] = fmaxf(cosL, EPSC);
        }
        const float fe = inv_e * sA;
        ((uint32_t*)g_A8)[(size_t)r*128 + tid] = pack4_e4m3(v.x*fe, v.y*fe, v.z*fe, v.w*fe);
        __syncthreads();
    }
}

// ---------------- K2: fp8 GEMM (acc = K*cos) + fused exp row-sum ----------------
__global__ __launch_bounds__(256, 2) void k2_gemm(const float* __restrict__ wp) {
    extern __shared__ unsigned char dyns[];
    const uint32_t sb = smem_u32(dyns);
    float* rowAcc = (float*)(dyns + OFF_ACC);

    const int tid = threadIdx.x;
    const int lane = tid & 31;
    const int warp = tid >> 5;
    const int wm = warp >> 2;     // 0..1: 64 rows
    const int wn = warp & 3;      // 0..3: 32 cols
    const int rowBase = blockIdx.x * MT;
    const float K = (*wp) * LOG2E;
    const float cK = K * EPSC;

    if (tid < MT) rowAcc[tid] = 0.f;

    // ---- A resident load: 4 slices x 16KB, SW128 ----
    #pragma unroll
    for (int q = 0; q < 16; q++) {
        const int u = tid + 256*q;
        const int s = u >> 10, v = u & 1023;
        const int r = v >> 3, kc = v & 7;
        cp_cg16(sb + (uint32_t)(s*SLICE_B + r*128 + ((kc*16) ^ ((r & 7) << 4))),
                g_A8 + (size_t)(rowBase + r)*DDIM + s*128 + kc*16);
    }
    asm volatile("cp.async.commit_group;\n");

    // ---- B slice loader ----
    auto loadB = [&](int g, int buf) {
        const int nc = g >> 2, sc = g & 3;
        #pragma unroll
        for (int q = 0; q < 4; q++) {
            const int u = tid + 256*q;
            const int r = u >> 3, kc = u & 7;
            cp_cg16(sb + (uint32_t)(OFF_B + buf*SLICE_B + r*128 + ((kc*16) ^ ((r & 7) << 4))),
                    g_B8 + (size_t)(nc*128 + r)*DDIM + sc*128 + kc*16);
        }
        asm volatile("cp.async.commit_group;\n");
    };
    loadB(0, 0);

    // ---- ldmatrix lane address precompute ----
    const int grp = lane >> 3, wi = lane & 7;
    uint32_t aBase[4], aMask[4];
    const uint32_t aB16 = (uint32_t)((grp >> 1) * 16);
    #pragma unroll
    for (int mt = 0; mt < 4; mt++) {
        const int row = wm*64 + mt*16 + (grp & 1)*8 + wi;
        aBase[mt] = sb + (uint32_t)(row * 128);
        aMask[mt] = (uint32_t)((row & 7) << 4);
    }
    uint32_t bBase[2], bMask[2];
    const uint32_t bB16 = (uint32_t)((grp & 1) * 16);
    #pragma unroll
    for (int p = 0; p < 2; p++) {
        const int row = wn*32 + p*16 + (grp >> 1)*8 + wi;
        bBase[p] = sb + OFF_B + (uint32_t)(row * 128);
        bMask[p] = (uint32_t)((row & 7) << 4);
    }

    float rs[8];
    #pragma unroll
    for (int k = 0; k < 8; k++) rs[k] = 0.f;

    for (int nc = 0; nc < NCHUNK; nc++) {
        float acc[4][4][4];
        #pragma unroll
        for (int x = 0; x < 4; x++)
            #pragma unroll
            for (int y = 0; y < 4; y++)
                #pragma unroll
                for (int z = 0; z < 4; z++) acc[x][y][z] = 0.f;

        for (int sc = 0; sc < 4; sc++) {
            const int g = nc*4 + sc;
            if (g + 1 < NCHUNK*4) {
                loadB(g + 1, (g + 1) & 1);
                asm volatile("cp.async.wait_group 1;\n");
            } else {
                asm volatile("cp.async.wait_group 0;\n");
            }
            __syncthreads();

            const uint32_t aSl = (uint32_t)(sc * SLICE_B);
            const uint32_t bBuf = (uint32_t)((g & 1) * SLICE_B);
            #pragma unroll
            for (int kk = 0; kk < 4; kk++) {
                uint32_t afr[4][4];
                #pragma unroll
                for (int mt = 0; mt < 4; mt++)
                    ldsm4(afr[mt], aBase[mt] + aSl + (((uint32_t)(kk*32) | aB16) ^ aMask[mt]));
                uint32_t bfr[4][2];
                #pragma unroll
                for (int p = 0; p < 2; p++) {
                    uint32_t t[4];
                    ldsm4(t, bBase[p] + bBuf + (((uint32_t)(kk*32) | bB16) ^ bMask[p]));
                    bfr[2*p][0] = t[0]; bfr[2*p][1] = t[1];
                    bfr[2*p+1][0] = t[2]; bfr[2*p+1][1] = t[3];
                }
                #pragma unroll
                for (int mt = 0; mt < 4; mt++)
                    #pragma unroll
                    for (int nt = 0; nt < 4; nt++)
                        mma_e4m3(acc[mt][nt], afr[mt], bfr[nt]);
            }
            __syncthreads();
        }

        // epilogue: acc already = K*cos ; rowsum += 2^max(acc, K*eps)
        #pragma unroll
        for (int mt = 0; mt < 4; mt++) {
            float s0 = rs[mt*2], s1 = rs[mt*2+1];
            #pragma unroll
            for (int nt = 0; nt < 4; nt++) {
                s0 += ex2f(fmaxf(acc[mt][nt][0], cK));
                s0 += ex2f(fmaxf(acc[mt][nt][1], cK));
                s1 += ex2f(fmaxf(acc[mt][nt][2], cK));
                s1 += ex2f(fmaxf(acc[mt][nt][3], cK));
            }
            rs[mt*2] = s0; rs[mt*2+1] = s1;
        }
    }

    // ---- final row reduction ----
    const int g8 = lane >> 2, tt = lane & 3;
    #pragma unroll
    for (int k = 0; k < 8; k++) {
        float v = rs[k];
        v += __shfl_xor_sync(0xffffffffu, v, 1);
        v += __shfl_xor_sync(0xffffffffu, v, 2);
        if (tt == 0)
            atomicAdd(&rowAcc[wm*64 + (k >> 1)*16 + (k & 1)*8 + g8], v);
    }
    __syncthreads();
    if (tid < MT) g_rowsum[rowBase + tid] = rowAcc[tid];
}

// ---------------- K3: per-row loss + global sum ----------------
__global__ __launch_bounds__(256) void k3_final(float* out, const float* __restrict__ wp) {
    const int r = blockIdx.x * 256 + threadIdx.x;
    const float w = *wp, K = w * LOG2E;
    const float fF = g_cosF[r], fL = g_cosL[r];
    float v = __logf(g_rowsum[r] - ex2f(K * fF) + ex2f(K * fL)) - w * fL;
    #pragma unroll
    for (int o = 16; o; o >>= 1) v += __shfl_xor_sync(0xffffffffu, v, o);
    __shared__ float sred[8];
    if ((threadIdx.x & 31) == 0) sred[threadIdx.x >> 5] = v;
    __syncthreads();
    if (threadIdx.x == 0) {
        float t = 0.f;
        #pragma unroll
        for (int i = 0; i < 8; i++) t += sred[i];
        atomicAdd(out, t);
    }
}

// ---------------- launcher ----------------
extern "C" void kernel_launch(void* const* d_in, const int* in_sizes, int n_in,
                              void* d_out, int out_size) {
    const float* dvecs = (const float*)d_in[0];
    const float* wp    = (const float*)d_in[1];
    float* out = (float*)d_out;

    cudaFuncSetAttribute(k2_gemm, cudaFuncAttributeMaxDynamicSharedMemorySize, SMEM_K2);

    k0_zero<<<1, 1>>>(out);
    k1_prep<<<NSPK, 128>>>(dvecs, wp);
    k2_gemm<<<NROWS/MT, 256, SMEM_K2>>>(wp);
    k3_final<<<NROWS/256, 256>>>(out, wp);
}

// round 4
// speedup vs baseline: 1.3711x; 1.1342x over previous
#include <cuda_runtime.h>
#include <cuda_bf16.h>
#include <cuda_fp16.h>
#include <cstdint>

#define NSPK 2048
#define MUTT 16
#define DDIM 512
#define NROWS (NSPK*MUTT)
#define EPSC 1e-6f
#define LOG2E 1.4426950408889634f

// ---- k2 tiling: 128 rows/CTA, 16 col-chunks of 128, K in 4 slices of 128 fp8 ----
#define MT 128
#define NCHUNK 16
#define TOTSLICE (NCHUNK*4)
#define SLICE_B 16384           // 128 x 128 bytes
#define OFF_B   65536           // A resident: 4 slices x 16KB
#define SMEM_K2 (OFF_B + 3*SLICE_B)   // 114688; rowAcc overlays OFF_B after mainloop

// ---- scratch ----
__device__ __align__(256) uint8_t g_A8[NROWS*DDIM];   // rows * sqrt(K), e4m3
__device__ __align__(256) uint8_t g_B8[NSPK*DDIM];    // centroids * sqrt(K), e4m3
__device__ float g_cosF[NROWS];
__device__ float g_cosL[NROWS];

// ---------------- helpers ----------------
__device__ __forceinline__ uint32_t smem_u32(const void* p) {
    uint32_t a;
    asm("{ .reg .u64 t; cvta.to.shared.u64 t, %1; cvt.u32.u64 %0, t; }" : "=r"(a) : "l"(p));
    return a;
}
__device__ __forceinline__ void cp_cg16(uint32_t dst, const void* src) {
    asm volatile("cp.async.cg.shared.global [%0], [%1], 16;" :: "r"(dst), "l"(src));
}
__device__ __forceinline__ void ldsm4(uint32_t r[4], uint32_t addr) {
    asm volatile("ldmatrix.sync.aligned.m8n8.x4.shared.b16 {%0,%1,%2,%3}, [%4];"
                 : "=r"(r[0]), "=r"(r[1]), "=r"(r[2]), "=r"(r[3]) : "r"(addr));
}
// fp8 mma with f16 accumulators (2 packed regs)
__device__ __forceinline__ void mma_e4m3_h(uint32_t c[2], const uint32_t a[4], const uint32_t b[2]) {
    asm volatile("mma.sync.aligned.m16n8k32.row.col.f16.e4m3.e4m3.f16 "
                 "{%0,%1}, {%2,%3,%4,%5}, {%6,%7}, {%0,%1};"
                 : "+r"(c[0]), "+r"(c[1])
                 : "r"(a[0]), "r"(a[1]), "r"(a[2]), "r"(a[3]), "r"(b[0]), "r"(b[1]));
}
__device__ __forceinline__ float ex2f(float x) {
    float y; asm("ex2.approx.ftz.f32 %0, %1;" : "=f"(y) : "f"(x)); return y;
}
__device__ __forceinline__ uint32_t ex2_h2(uint32_t x) {
    uint32_t y; asm("ex2.approx.f16x2 %0, %1;" : "=r"(y) : "r"(x)); return y;
}
__device__ __forceinline__ uint32_t pack4_e4m3(float v0, float v1, float v2, float v3) {
    uint16_t lo, hi;
    asm("cvt.rn.satfinite.e4m3x2.f32 %0, %1, %2;" : "=h"(lo) : "f"(v1), "f"(v0));
    asm("cvt.rn.satfinite.e4m3x2.f32 %0, %1, %2;" : "=h"(hi) : "f"(v3), "f"(v2));
    return (uint32_t)lo | ((uint32_t)hi << 16);
}

// ---------------- K1: per-speaker prep -> fp8 scaled by sqrt(w*log2e) ----------------
// also zeroes the output scalar (block 0)
__global__ __launch_bounds__(128) void k1_prep(const float* __restrict__ dvecs,
                                               const float* __restrict__ wp,
                                               float* out) {
    __shared__ float tile[MUTT*DDIM];
    __shared__ float4 sS[128];
    __shared__ float red[4];

    const int j = blockIdx.x, tid = threadIdx.x;
    const int lane = tid & 31, wid = tid >> 5;
    const float w = *wp;
    const float sA = sqrtf(w * LOG2E);
    if (j == 0 && tid == 0) out[0] = 0.f;

    const float4* src = (const float4*)(dvecs + (size_t)j * MUTT * DDIM);
    float4* t4 = (float4*)tile;
    #pragma unroll
    for (int q = 0; q < 16; q++) t4[tid + 128*q] = src[tid + 128*q];
    __syncthreads();

    // centroid: per-thread 4 dims
    const float4* t4c = (const float4*)tile;
    float4 s = make_float4(0.f, 0.f, 0.f, 0.f);
    #pragma unroll
    for (int i = 0; i < MUTT; i++) {
        const float4 v = t4c[i*128 + tid];
        s.x += v.x; s.y += v.y; s.z += v.z; s.w += v.w;
    }
    sS[tid] = s;
    float ssqp = s.x*s.x + s.y*s.y + s.z*s.z + s.w*s.w;
    #pragma unroll
    for (int o = 16; o; o >>= 1) ssqp += __shfl_xor_sync(0xffffffffu, ssqp, o);
    if (lane == 0) red[wid] = ssqp;
    __syncthreads();
    const float ssq = red[0] + red[1] + red[2] + red[3];
    const float inv_S = rsqrtf(ssq);

    const float fB = inv_S * sA;
    ((uint32_t*)g_B8)[(size_t)j*128 + tid] = pack4_e4m3(s.x*fB, s.y*fB, s.z*fB, s.w*fB);

    // warp-per-utterance: warp w handles i = w, w+4, w+8, w+12 (no further syncs)
    #pragma unroll
    for (int q = 0; q < 4; q++) {
        const int i = wid + 4*q;
        float4 v[4]; float dp = 0.f, ep = 0.f;
        #pragma unroll
        for (int c = 0; c < 4; c++) {
            v[c] = t4c[i*128 + lane + 32*c];
            const float4 Sv = sS[lane + 32*c];
            dp += v[c].x*Sv.x + v[c].y*Sv.y + v[c].z*Sv.z + v[c].w*Sv.w;
            ep += v[c].x*v[c].x + v[c].y*v[c].y + v[c].z*v[c].z + v[c].w*v[c].w;
        }
        #pragma unroll
        for (int o = 16; o; o >>= 1) {
            dp += __shfl_xor_sync(0xffffffffu, dp, o);
            ep += __shfl_xor_sync(0xffffffffu, ep, o);
        }
        const float inv_e = rsqrtf(ep);
        const int r = j * MUTT + i;
        if (lane == 0) {
            const float cosF = dp * inv_e * inv_S;
            const float den  = fmaxf(ssq - 2.f*dp + ep, 1e-20f);
            const float cosL = (dp - ep) * inv_e * rsqrtf(den);
            g_cosF[r] = fmaxf(cosF, EPSC);
            g_cosL[r] = fmaxf(cosL, EPSC);
        }
        const float fe = inv_e * sA;
        #pragma unroll
        for (int c = 0; c < 4; c++)
            ((uint32_t*)g_A8)[(size_t)r*128 + lane + 32*c] =
                pack4_e4m3(v[c].x*fe, v[c].y*fe, v[c].z*fe, v[c].w*fe);
    }
}

// ---------------- K2: fp8 GEMM (f16 acc = K*cos) + fused exp row-sum + loss ----------------
__global__ __launch_bounds__(256, 2) void k2_gemm(const float* __restrict__ wp, float* out) {
    extern __shared__ unsigned char dyns[];
    const uint32_t sb = smem_u32(dyns);

    const int tid = threadIdx.x;
    const int lane = tid & 31;
    const int warp = tid >> 5;
    const int wm = warp >> 2;     // 0..1: 64 rows
    const int wn = warp & 3;      // 0..3: 32 cols
    const int rowBase = blockIdx.x * MT;
    const float w = *wp;
    const float K = w * LOG2E;
    const __half2 cKh = __float2half2_rn(K * EPSC);

    // ---- A resident load: 4 slices x 16KB, SW128 ----
    #pragma unroll
    for (int q = 0; q < 16; q++) {
        const int u = tid + 256*q;
        const int ss = u >> 10, v = u & 1023;
        const int r = v >> 3, kc = v & 7;
        cp_cg16(sb + (uint32_t)(ss*SLICE_B + r*128 + ((kc*16) ^ ((r & 7) << 4))),
                g_A8 + (size_t)(rowBase + r)*DDIM + ss*128 + kc*16);
    }
    asm volatile("cp.async.commit_group;\n");

    auto loadB = [&](int g, int buf) {
        const int nc = g >> 2, sc = g & 3;
        #pragma unroll
        for (int q = 0; q < 4; q++) {
            const int u = tid + 256*q;
            const int r = u >> 3, kc = u & 7;
            cp_cg16(sb + (uint32_t)(OFF_B + buf*SLICE_B + r*128 + ((kc*16) ^ ((r & 7) << 4))),
                    g_B8 + (size_t)(nc*128 + r)*DDIM + sc*128 + kc*16);
        }
        asm volatile("cp.async.commit_group;\n");
    };
    loadB(0, 0);
    loadB(1, 1);

    // ---- ldmatrix lane addresses ----
    const int grp = lane >> 3, wi = lane & 7;
    uint32_t aBase[4], aMask[4];
    const uint32_t aB16 = (uint32_t)((grp >> 1) * 16);
    #pragma unroll
    for (int mt = 0; mt < 4; mt++) {
        const int row = wm*64 + mt*16 + (grp & 1)*8 + wi;
        aBase[mt] = sb + (uint32_t)(row * 128);
        aMask[mt] = (uint32_t)((row & 7) << 4);
    }
    uint32_t bBase[2], bMask[2];
    const uint32_t bB16 = (uint32_t)((grp & 1) * 16);
    #pragma unroll
    for (int p = 0; p < 2; p++) {
        const int row = wn*32 + p*16 + (grp >> 1)*8 + wi;
        bBase[p] = sb + OFF_B + (uint32_t)(row * 128);
        bMask[p] = (uint32_t)((row & 7) << 4);
    }

    float rs[8];
    #pragma unroll
    for (int k = 0; k < 8; k++) rs[k] = 0.f;

    int buf = 0;
    for (int nc = 0; nc < NCHUNK; nc++) {
        uint32_t acc[4][4][2];
        #pragma unroll
        for (int x = 0; x < 4; x++)
            #pragma unroll
            for (int y = 0; y < 4; y++) { acc[x][y][0] = 0u; acc[x][y][1] = 0u; }

        for (int sc = 0; sc < 4; sc++) {
            const int g = nc*4 + sc;
            if (g < TOTSLICE - 2) {
                int pbuf = buf + 2; if (pbuf >= 3) pbuf -= 3;
                loadB(g + 2, pbuf);
                asm volatile("cp.async.wait_group 2;\n");
            } else if (g == TOTSLICE - 2) {
                asm volatile("cp.async.wait_group 1;\n");
            } else {
                asm volatile("cp.async.wait_group 0;\n");
            }
            __syncthreads();

            const uint32_t aSl = (uint32_t)(sc * SLICE_B);
            const uint32_t bBuf = (uint32_t)(buf * SLICE_B);
            #pragma unroll
            for (int kk = 0; kk < 4; kk++) {
                uint32_t afr[4][4];
                #pragma unroll
                for (int mt = 0; mt < 4; mt++)
                    ldsm4(afr[mt], aBase[mt] + aSl + (((uint32_t)(kk*32) | aB16) ^ aMask[mt]));
                uint32_t bfr[4][2];
                #pragma unroll
                for (int p = 0; p < 2; p++) {
                    uint32_t t[4];
                    ldsm4(t, bBase[p] + bBuf + (((uint32_t)(kk*32) | bB16) ^ bMask[p]));
                    bfr[2*p][0] = t[0]; bfr[2*p][1] = t[1];
                    bfr[2*p+1][0] = t[2]; bfr[2*p+1][1] = t[3];
                }
                #pragma unroll
                for (int mt = 0; mt < 4; mt++)
                    #pragma unroll
                    for (int nt = 0; nt < 4; nt++)
                        mma_e4m3_h(acc[mt][nt], afr[mt], bfr[nt]);
            }
            if (++buf >= 3) buf -= 3;
        }

        // epilogue: acc halves = K*cos ; rowsum += 2^max(acc, K*eps)
        #pragma unroll
        for (int mt = 0; mt < 4; mt++) {
            float s0 = rs[mt*2], s1 = rs[mt*2+1];
            #pragma unroll
            for (int nt = 0; nt < 4; nt++) {
                __half2 h0 = __hmax2(*(__half2*)&acc[mt][nt][0], cKh);
                __half2 h1 = __hmax2(*(__half2*)&acc[mt][nt][1], cKh);
                const uint32_t e0 = ex2_h2(*(uint32_t*)&h0);
                const uint32_t e1 = ex2_h2(*(uint32_t*)&h1);
                const float2 f0 = __half22float2(*(__half2*)&e0);
                const float2 f1 = __half22float2(*(__half2*)&e1);
                s0 += f0.x + f0.y;
                s1 += f1.x + f1.y;
            }
            rs[mt*2] = s0; rs[mt*2+1] = s1;
        }
    }

    // ---- row reduction into smem (overlay on B buffer 0; mainloop fully drained) ----
    __syncthreads();
    float* rowAcc = (float*)(dyns + OFF_B);
    float* red = (float*)(dyns + OFF_B + 512);
    if (tid < MT) rowAcc[tid] = 0.f;
    __syncthreads();

    const int g8 = lane >> 2, tt = lane & 3;
    #pragma unroll
    for (int k = 0; k < 8; k++) {
        float v = rs[k];
        v += __shfl_xor_sync(0xffffffffu, v, 1);
        v += __shfl_xor_sync(0xffffffffu, v, 2);
        if (tt == 0)
            atomicAdd(&rowAcc[wm*64 + (k >> 1)*16 + (k & 1)*8 + g8], v);
    }
    __syncthreads();

    // ---- per-row loss + block sum + global atomic ----
    float v = 0.f;
    if (tid < MT) {
        const int r = rowBase + tid;
        const float fF = g_cosF[r], fL = g_cosL[r];
        v = __logf(rowAcc[tid] - ex2f(K * fF) + ex2f(K * fL)) - w * fL;
    }
    #pragma unroll
    for (int o = 16; o; o >>= 1) v += __shfl_xor_sync(0xffffffffu, v, o);
    if (lane == 0) red[warp] = v;
    __syncthreads();
    if (tid == 0) {
        float t = 0.f;
        #pragma unroll
        for (int i = 0; i < 8; i++) t += red[i];
        atomicAdd(out, t);
    }
}

// ---------------- launcher ----------------
extern "C" void kernel_launch(void* const* d_in, const int* in_sizes, int n_in,
                              void* d_out, int out_size) {
    const float* dvecs = (const float*)d_in[0];
    const float* wp    = (const float*)d_in[1];
    float* out = (float*)d_out;

    cudaFuncSetAttribute(k2_gemm, cudaFuncAttributeMaxDynamicSharedMemorySize, SMEM_K2);

    k1_prep<<<NSPK, 128>>>(dvecs, wp, out);
    k2_gemm<<<NROWS/MT, 256, SMEM_K2>>>(wp, out);
}

// round 5
// speedup vs baseline: 1.4073x; 1.0264x over previous
#include <cuda_runtime.h>
#include <cuda_bf16.h>
#include <cuda_fp16.h>
#include <cstdint>

#define NSPK 2048
#define MUTT 16
#define DDIM 512
#define NROWS (NSPK*MUTT)
#define EPSC 1e-6f
#define LOG2E 1.4426950408889634f

// ---- k2 tiling: 128 rows x 1024 cols per CTA (split-N), K in 4 slices of 128 fp8 ----
#define MT 128
#define NCH_CTA 8               // 8 col-chunks of 128 per CTA
#define NSLICE (NCH_CTA*4)      // 32 K-slices per CTA
#define SLICE_B 16384           // 128 x 128 bytes
#define OFF_B   65536           // A resident: 4 slices x 16KB
#define SMEM_K2 (OFF_B + 2*SLICE_B + 512)   // 98816 -> 2 CTAs/SM comfortably

// ---- scratch ----
__device__ __align__(256) uint8_t g_A8[NROWS*DDIM];   // rows * sqrt(K), e4m3
__device__ __align__(256) uint8_t g_B8[NSPK*DDIM];    // centroids * sqrt(K), e4m3
__device__ float g_rowsum[NROWS];
__device__ float g_cosF[NROWS];
__device__ float g_cosL[NROWS];

// ---------------- helpers ----------------
__device__ __forceinline__ uint32_t smem_u32(const void* p) {
    uint32_t a;
    asm("{ .reg .u64 t; cvta.to.shared.u64 t, %1; cvt.u32.u64 %0, t; }" : "=r"(a) : "l"(p));
    return a;
}
__device__ __forceinline__ void cp_cg16(uint32_t dst, const void* src) {
    asm volatile("cp.async.cg.shared.global [%0], [%1], 16;" :: "r"(dst), "l"(src));
}
__device__ __forceinline__ void ldsm4(uint32_t r[4], uint32_t addr) {
    asm volatile("ldmatrix.sync.aligned.m8n8.x4.shared.b16 {%0,%1,%2,%3}, [%4];"
                 : "=r"(r[0]), "=r"(r[1]), "=r"(r[2]), "=r"(r[3]) : "r"(addr));
}
__device__ __forceinline__ void mma_e4m3_h(uint32_t c[2], const uint32_t a[4], const uint32_t b[2]) {
    asm volatile("mma.sync.aligned.m16n8k32.row.col.f16.e4m3.e4m3.f16 "
                 "{%0,%1}, {%2,%3,%4,%5}, {%6,%7}, {%0,%1};"
                 : "+r"(c[0]), "+r"(c[1])
                 : "r"(a[0]), "r"(a[1]), "r"(a[2]), "r"(a[3]), "r"(b[0]), "r"(b[1]));
}
__device__ __forceinline__ float ex2f(float x) {
    float y; asm("ex2.approx.ftz.f32 %0, %1;" : "=f"(y) : "f"(x)); return y;
}
__device__ __forceinline__ __half2 ex2_h2(__half2 x) {
    __half2 y;
    asm("ex2.approx.f16x2 %0, %1;" : "=r"(*(uint32_t*)&y) : "r"(*(const uint32_t*)&x));
    return y;
}
__device__ __forceinline__ uint32_t pack4_e4m3(float v0, float v1, float v2, float v3) {
    uint16_t lo, hi;
    asm("cvt.rn.satfinite.e4m3x2.f32 %0, %1, %2;" : "=h"(lo) : "f"(v1), "f"(v0));
    asm("cvt.rn.satfinite.e4m3x2.f32 %0, %1, %2;" : "=h"(hi) : "f"(v3), "f"(v2));
    return (uint32_t)lo | ((uint32_t)hi << 16);
}

// ---------------- K1: per-speaker prep -> fp8 scaled by sqrt(w*log2e) ----------------
// also zeroes out[0] and this speaker's g_rowsum entries
__global__ __launch_bounds__(128) void k1_prep(const float* __restrict__ dvecs,
                                               const float* __restrict__ wp,
                                               float* out) {
    __shared__ float tile[MUTT*DDIM];
    __shared__ float4 sS[128];
    __shared__ float red[4];

    const int j = blockIdx.x, tid = threadIdx.x;
    const int lane = tid & 31, wid = tid >> 5;
    const float w = *wp;
    const float sA = sqrtf(w * LOG2E);
    if (j == 0 && tid == 0) out[0] = 0.f;
    if (tid < MUTT) g_rowsum[j*MUTT + tid] = 0.f;

    const float4* src = (const float4*)(dvecs + (size_t)j * MUTT * DDIM);
    float4* t4 = (float4*)tile;
    #pragma unroll
    for (int q = 0; q < 16; q++) t4[tid + 128*q] = src[tid + 128*q];
    __syncthreads();

    const float4* t4c = (const float4*)tile;
    float4 s = make_float4(0.f, 0.f, 0.f, 0.f);
    #pragma unroll
    for (int i = 0; i < MUTT; i++) {
        const float4 v = t4c[i*128 + tid];
        s.x += v.x; s.y += v.y; s.z += v.z; s.w += v.w;
    }
    sS[tid] = s;
    float ssqp = s.x*s.x + s.y*s.y + s.z*s.z + s.w*s.w;
    #pragma unroll
    for (int o = 16; o; o >>= 1) ssqp += __shfl_xor_sync(0xffffffffu, ssqp, o);
    if (lane == 0) red[wid] = ssqp;
    __syncthreads();
    const float ssq = red[0] + red[1] + red[2] + red[3];
    const float inv_S = rsqrtf(ssq);

    const float fB = inv_S * sA;
    ((uint32_t*)g_B8)[(size_t)j*128 + tid] = pack4_e4m3(s.x*fB, s.y*fB, s.z*fB, s.w*fB);

    #pragma unroll
    for (int q = 0; q < 4; q++) {
        const int i = wid + 4*q;
        float4 v[4]; float dp = 0.f, ep = 0.f;
        #pragma unroll
        for (int c = 0; c < 4; c++) {
            v[c] = t4c[i*128 + lane + 32*c];
            const float4 Sv = sS[lane + 32*c];
            dp += v[c].x*Sv.x + v[c].y*Sv.y + v[c].z*Sv.z + v[c].w*Sv.w;
            ep += v[c].x*v[c].x + v[c].y*v[c].y + v[c].z*v[c].z + v[c].w*v[c].w;
        }
        #pragma unroll
        for (int o = 16; o; o >>= 1) {
            dp += __shfl_xor_sync(0xffffffffu, dp, o);
            ep += __shfl_xor_sync(0xffffffffu, ep, o);
        }
        const float inv_e = rsqrtf(ep);
        const int r = j * MUTT + i;
        if (lane == 0) {
            const float cosF = dp * inv_e * inv_S;
            const float den  = fmaxf(ssq - 2.f*dp + ep, 1e-20f);
            const float cosL = (dp - ep) * inv_e * rsqrtf(den);
            g_cosF[r] = fmaxf(cosF, EPSC);
            g_cosL[r] = fmaxf(cosL, EPSC);
        }
        const float fe = inv_e * sA;
        #pragma unroll
        for (int c = 0; c < 4; c++)
            ((uint32_t*)g_A8)[(size_t)r*128 + lane + 32*c] =
                pack4_e4m3(v[c].x*fe, v[c].y*fe, v[c].z*fe, v[c].w*fe);
    }
}

// ---------------- K2: fp8 GEMM (f16 acc = K*cos) + fused exp row-sum ----------------
// grid = 512: blockIdx -> (rowBlock = bx>>1, colHalf = bx&1)
__global__ __launch_bounds__(256, 2) void k2_gemm(const float* __restrict__ wp) {
    extern __shared__ unsigned char dyns[];
    const uint32_t sb = smem_u32(dyns);

    const int tid = threadIdx.x;
    const int lane = tid & 31;
    const int warp = tid >> 5;
    const int wm = warp >> 2;     // 0..1: 64 rows
    const int wn = warp & 3;      // 0..3: 32 cols
    const int rowBase = (blockIdx.x >> 1) * MT;
    const int colBase = (blockIdx.x & 1) * NCH_CTA;   // in chunks of 128
    const float K = (*wp) * LOG2E;
    const __half2 cKh = __float2half2_rn(K * EPSC);

    // ---- A resident load: 4 slices x 16KB, SW128 ----
    #pragma unroll
    for (int q = 0; q < 16; q++) {
        const int u = tid + 256*q;
        const int ss = u >> 10, v = u & 1023;
        const int r = v >> 3, kc = v & 7;
        cp_cg16(sb + (uint32_t)(ss*SLICE_B + r*128 + ((kc*16) ^ ((r & 7) << 4))),
                g_A8 + (size_t)(rowBase + r)*DDIM + ss*128 + kc*16);
    }
    asm volatile("cp.async.commit_group;\n");

    auto loadB = [&](int s, int buf) {
        const int nc = colBase + (s >> 2), sc = s & 3;
        #pragma unroll
        for (int q = 0; q < 4; q++) {
            const int u = tid + 256*q;
            const int r = u >> 3, kc = u & 7;
            cp_cg16(sb + (uint32_t)(OFF_B + buf*SLICE_B + r*128 + ((kc*16) ^ ((r & 7) << 4))),
                    g_B8 + (size_t)(nc*128 + r)*DDIM + sc*128 + kc*16);
        }
        asm volatile("cp.async.commit_group;\n");
    };
    loadB(0, 0);
    loadB(1, 1);

    // ---- ldmatrix lane addresses ----
    const int grp = lane >> 3, wi = lane & 7;
    uint32_t aBase[4], aMask[4];
    const uint32_t aB16 = (uint32_t)((grp >> 1) * 16);
    #pragma unroll
    for (int mt = 0; mt < 4; mt++) {
        const int row = wm*64 + mt*16 + (grp & 1)*8 + wi;
        aBase[mt] = sb + (uint32_t)(row * 128);
        aMask[mt] = (uint32_t)((row & 7) << 4);
    }
    uint32_t bBase[2], bMask[2];
    const uint32_t bB16 = (uint32_t)((grp & 1) * 16);
    #pragma unroll
    for (int p = 0; p < 2; p++) {
        const int row = wn*32 + p*16 + (grp >> 1)*8 + wi;
        bBase[p] = sb + OFF_B + (uint32_t)(row * 128);
        bMask[p] = (uint32_t)((row & 7) << 4);
    }

    float rs[8];
    #pragma unroll
    for (int k = 0; k < 8; k++) rs[k] = 0.f;

    for (int c8 = 0; c8 < NCH_CTA; c8++) {
        uint32_t acc[4][4][2];
        #pragma unroll
        for (int x = 0; x < 4; x++)
            #pragma unroll
            for (int y = 0; y < 4; y++) { acc[x][y][0] = 0u; acc[x][y][1] = 0u; }

        #pragma unroll
        for (int sc = 0; sc < 4; sc++) {
            const int s = c8*4 + sc;
            if (s < NSLICE - 1) asm volatile("cp.async.wait_group 1;\n");
            else                asm volatile("cp.async.wait_group 0;\n");
            __syncthreads();

            const uint32_t aSl = (uint32_t)(sc * SLICE_B);
            const uint32_t bBuf = (uint32_t)((s & 1) * SLICE_B);
            #pragma unroll
            for (int kk = 0; kk < 4; kk++) {
                uint32_t afr[4][4];
                #pragma unroll
                for (int mt = 0; mt < 4; mt++)
                    ldsm4(afr[mt], aBase[mt] + aSl + (((uint32_t)(kk*32) | aB16) ^ aMask[mt]));
                uint32_t bfr[4][2];
                #pragma unroll
                for (int p = 0; p < 2; p++) {
                    uint32_t t[4];
                    ldsm4(t, bBase[p] + bBuf + (((uint32_t)(kk*32) | bB16) ^ bMask[p]));
                    bfr[2*p][0] = t[0]; bfr[2*p][1] = t[1];
                    bfr[2*p+1][0] = t[2]; bfr[2*p+1][1] = t[3];
                }
                #pragma unroll
                for (int mt = 0; mt < 4; mt++)
                    #pragma unroll
                    for (int nt = 0; nt < 4; nt++)
                        mma_e4m3_h(acc[mt][nt], afr[mt], bfr[nt]);
            }
            __syncthreads();
            if (s + 2 < NSLICE) loadB(s + 2, s & 1);
        }

        // epilogue: acc halves = K*cos ; f16 hadd2 across nt, then one f32 convert
        #pragma unroll
        for (int mt = 0; mt < 4; mt++) {
            __half2 h0 = ex2_h2(__hmax2(*(__half2*)&acc[mt][0][0], cKh));
            __half2 h1 = ex2_h2(__hmax2(*(__half2*)&acc[mt][0][1], cKh));
            #pragma unroll
            for (int nt = 1; nt < 4; nt++) {
                h0 = __hadd2(h0, ex2_h2(__hmax2(*(__half2*)&acc[mt][nt][0], cKh)));
                h1 = __hadd2(h1, ex2_h2(__hmax2(*(__half2*)&acc[mt][nt][1], cKh)));
            }
            const float2 f0 = __half22float2(h0);
            const float2 f1 = __half22float2(h1);
            rs[mt*2]   += f0.x + f0.y;
            rs[mt*2+1] += f1.x + f1.y;
        }
    }

    // ---- row reduction into smem (overlay on B buffers; mainloop fully drained) ----
    float* rowAcc = (float*)(dyns + OFF_B);
    if (tid < MT) rowAcc[tid] = 0.f;
    __syncthreads();

    const int g8 = lane >> 2, tt = lane & 3;
    #pragma unroll
    for (int k = 0; k < 8; k++) {
        float v = rs[k];
        v += __shfl_xor_sync(0xffffffffu, v, 1);
        v += __shfl_xor_sync(0xffffffffu, v, 2);
        if (tt == 0)
            atomicAdd(&rowAcc[wm*64 + (k >> 1)*16 + (k & 1)*8 + g8], v);
    }
    __syncthreads();

    if (tid < MT) atomicAdd(&g_rowsum[rowBase + tid], rowAcc[tid]);
}

// ---------------- K3: per-row loss + global sum ----------------
__global__ __launch_bounds__(256) void k3_final(float* out, const float* __restrict__ wp) {
    const int r = blockIdx.x * 256 + threadIdx.x;
    const float w = *wp, K = w * LOG2E;
    const float fF = g_cosF[r], fL = g_cosL[r];
    float v = __logf(g_rowsum[r] - ex2f(K * fF) + ex2f(K * fL)) - w * fL;
    #pragma unroll
    for (int o = 16; o; o >>= 1) v += __shfl_xor_sync(0xffffffffu, v, o);
    __shared__ float sred[8];
    if ((threadIdx.x & 31) == 0) sred[threadIdx.x >> 5] = v;
    __syncthreads();
    if (threadIdx.x == 0) {
        float t = 0.f;
        #pragma unroll
        for (int i = 0; i < 8; i++) t += sred[i];
        atomicAdd(out, t);
    }
}

// ---------------- launcher ----------------
extern "C" void kernel_launch(void* const* d_in, const int* in_sizes, int n_in,
                              void* d_out, int out_size) {
    const float* dvecs = (const float*)d_in[0];
    const float* wp    = (const float*)d_in[1];
    float* out = (float*)d_out;

    cudaFuncSetAttribute(k2_gemm, cudaFuncAttributeMaxDynamicSharedMemorySize, SMEM_K2);

    k1_prep<<<NSPK, 128>>>(dvecs, wp, out);
    k2_gemm<<<(NROWS/MT)*2, 256, SMEM_K2>>>(wp);
    k3_final<<<NROWS/256, 256>>>(out, wp);
}

// round 6
// speedup vs baseline: 1.5247x; 1.0834x over previous
#include <cuda_runtime.h>
#include <cuda_bf16.h>
#include <cuda_fp16.h>
#include <cstdint>

#define NSPK 2048
#define MUTT 16
#define DDIM 512
#define NROWS (NSPK*MUTT)
#define EPSC 1e-6f
#define LOG2E 1.4426950408889634f

// ---- k2 tiling: 128 rows x 512 cols per CTA (quarter tiles), K in 4 slices of 128 fp8 ----
#define MT 128
#define NCH_CTA 4               // 4 col-chunks of 128 per CTA
#define NSLICE (NCH_CTA*4)      // 16 K-slices per CTA
#define SLICE_B 16384           // 128 x 128 bytes
#define OFF_B   65536           // A resident: 4 slices x 16KB
#define SMEM_K2 (OFF_B + 3*SLICE_B)   // 114688; rowAcc overlays OFF_B after mainloop

// ---- scratch ----
__device__ __align__(256) uint8_t g_A8[NROWS*DDIM];   // rows * sqrt(K), e4m3
__device__ __align__(256) uint8_t g_B8[NSPK*DDIM];    // centroids * sqrt(K), e4m3
__device__ float g_rowsum[NROWS];
__device__ float g_cosF[NROWS];
__device__ float g_cosL[NROWS];
__device__ unsigned g_count[NROWS/MT];

// ---------------- helpers ----------------
__device__ __forceinline__ uint32_t smem_u32(const void* p) {
    uint32_t a;
    asm("{ .reg .u64 t; cvta.to.shared.u64 t, %1; cvt.u32.u64 %0, t; }" : "=r"(a) : "l"(p));
    return a;
}
__device__ __forceinline__ void cp_cg16(uint32_t dst, const void* src) {
    asm volatile("cp.async.cg.shared.global [%0], [%1], 16;" :: "r"(dst), "l"(src));
}
__device__ __forceinline__ void ldsm4(uint32_t r[4], uint32_t addr) {
    asm volatile("ldmatrix.sync.aligned.m8n8.x4.shared.b16 {%0,%1,%2,%3}, [%4];"
                 : "=r"(r[0]), "=r"(r[1]), "=r"(r[2]), "=r"(r[3]) : "r"(addr));
}
__device__ __forceinline__ void mma_e4m3_h(uint32_t c[2], const uint32_t a[4], const uint32_t b[2]) {
    asm volatile("mma.sync.aligned.m16n8k32.row.col.f16.e4m3.e4m3.f16 "
                 "{%0,%1}, {%2,%3,%4,%5}, {%6,%7}, {%0,%1};"
                 : "+r"(c[0]), "+r"(c[1])
                 : "r"(a[0]), "r"(a[1]), "r"(a[2]), "r"(a[3]), "r"(b[0]), "r"(b[1]));
}
__device__ __forceinline__ float ex2f(float x) {
    float y; asm("ex2.approx.ftz.f32 %0, %1;" : "=f"(y) : "f"(x)); return y;
}
__device__ __forceinline__ __half2 ex2_h2(__half2 x) {
    __half2 y;
    asm("ex2.approx.f16x2 %0, %1;" : "=r"(*(uint32_t*)&y) : "r"(*(const uint32_t*)&x));
    return y;
}
__device__ __forceinline__ uint32_t pack4_e4m3(float v0, float v1, float v2, float v3) {
    uint16_t lo, hi;
    asm("cvt.rn.satfinite.e4m3x2.f32 %0, %1, %2;" : "=h"(lo) : "f"(v1), "f"(v0));
    asm("cvt.rn.satfinite.e4m3x2.f32 %0, %1, %2;" : "=h"(hi) : "f"(v3), "f"(v2));
    return (uint32_t)lo | ((uint32_t)hi << 16);
}

// ---------------- K1: per-speaker prep (register-resident) ----------------
// thread t owns dims [4t, 4t+4) of all 16 utterances; single global read.
__global__ __launch_bounds__(128) void k1_prep(const float* __restrict__ dvecs,
                                               const float* __restrict__ wp,
                                               float* out) {
    __shared__ float2 sde[MUTT*128];   // (dp, ep) partials, 16KB
    __shared__ float  sfe[MUTT];       // inv_e * sA per utterance
    __shared__ float  red[4];

    const int j = blockIdx.x, tid = threadIdx.x;
    const int lane = tid & 31, wid = tid >> 5;
    const float w = *wp;
    const float sA = sqrtf(w * LOG2E);

    if (j == 0 && tid == 0) out[0] = 0.f;
    if (tid < MUTT) g_rowsum[j*MUTT + tid] = 0.f;
    if (j < NROWS/MT && tid == 64) g_count[j] = 0u;

    const float4* src = (const float4*)(dvecs + (size_t)j * MUTT * DDIM);
    float4 v[MUTT];
    #pragma unroll
    for (int i = 0; i < MUTT; i++) v[i] = src[i*128 + tid];

    // centroid sum (this thread's 4 dims)
    float4 s = make_float4(0.f, 0.f, 0.f, 0.f);
    #pragma unroll
    for (int i = 0; i < MUTT; i++) { s.x += v[i].x; s.y += v[i].y; s.z += v[i].z; s.w += v[i].w; }

    float ssqp = s.x*s.x + s.y*s.y + s.z*s.z + s.w*s.w;
    #pragma unroll
    for (int o = 16; o; o >>= 1) ssqp += __shfl_xor_sync(0xffffffffu, ssqp, o);
    if (lane == 0) red[wid] = ssqp;

    // dp/ep partials per utterance
    #pragma unroll
    for (int i = 0; i < MUTT; i++) {
        const float dp = v[i].x*s.x + v[i].y*s.y + v[i].z*s.z + v[i].w*s.w;
        const float ep = v[i].x*v[i].x + v[i].y*v[i].y + v[i].z*v[i].z + v[i].w*v[i].w;
        sde[i*128 + tid] = make_float2(dp, ep);
    }
    __syncthreads();

    const float ssq = red[0] + red[1] + red[2] + red[3];
    const float inv_S = rsqrtf(ssq);
    const float fB = inv_S * sA;
    ((uint32_t*)g_B8)[(size_t)j*128 + tid] = pack4_e4m3(s.x*fB, s.y*fB, s.z*fB, s.w*fB);

    // 4 warps x 4 utterances: reduce dp/ep, compute scalars
    #pragma unroll
    for (int q = 0; q < 4; q++) {
        const int i = wid + 4*q;
        float2 a0 = sde[i*128 + lane];
        const float2 a1 = sde[i*128 + lane + 32];
        const float2 a2 = sde[i*128 + lane + 64];
        const float2 a3 = sde[i*128 + lane + 96];
        float dp = a0.x + a1.x + a2.x + a3.x;
        float ep = a0.y + a1.y + a2.y + a3.y;
        #pragma unroll
        for (int o = 16; o; o >>= 1) {
            dp += __shfl_xor_sync(0xffffffffu, dp, o);
            ep += __shfl_xor_sync(0xffffffffu, ep, o);
        }
        if (lane == 0) {
            const float inv_e = rsqrtf(ep);
            const int r = j * MUTT + i;
            const float cosF = dp * inv_e * inv_S;
            const float den  = fmaxf(ssq - 2.f*dp + ep, 1e-20f);
            const float cosL = (dp - ep) * inv_e * rsqrtf(den);
            g_cosF[r] = fmaxf(cosF, EPSC);
            g_cosL[r] = fmaxf(cosL, EPSC);
            sfe[i] = inv_e * sA;
        }
    }
    __syncthreads();

    #pragma unroll
    for (int i = 0; i < MUTT; i++) {
        const float fe = sfe[i];
        ((uint32_t*)g_A8)[(size_t)(j*MUTT + i)*128 + tid] =
            pack4_e4m3(v[i].x*fe, v[i].y*fe, v[i].z*fe, v[i].w*fe);
    }
}

// ---------------- K2: fp8 GEMM (f16 acc = K*cos) + exp row-sum + fused loss ----------------
// grid = 1024: rowBlock = bx>>2 (128 rows), colQ = bx&3 (512 cols)
__global__ __launch_bounds__(256, 2) void k2_gemm(const float* __restrict__ wp, float* out) {
    extern __shared__ unsigned char dyns[];
    __shared__ int s_last;
    const uint32_t sb = smem_u32(dyns);

    const int tid = threadIdx.x;
    const int lane = tid & 31;
    const int warp = tid >> 5;
    const int wm = warp >> 2;     // 0..1: 64 rows
    const int wn = warp & 3;      // 0..3: 32 cols
    const int rowBlock = blockIdx.x >> 2;
    const int rowBase = rowBlock * MT;
    const int colBase = (blockIdx.x & 3) * NCH_CTA;   // chunk units of 128
    const float w = *wp;
    const float K = w * LOG2E;
    const __half2 cKh = __float2half2_rn(K * EPSC);

    // ---- A resident: 4 slices x 16KB, SW128 (one commit group) ----
    #pragma unroll
    for (int q = 0; q < 16; q++) {
        const int u = tid + 256*q;
        const int ss = u >> 10, vv = u & 1023;
        const int r = vv >> 3, kc = vv & 7;
        cp_cg16(sb + (uint32_t)(ss*SLICE_B + r*128 + ((kc*16) ^ ((r & 7) << 4))),
                g_A8 + (size_t)(rowBase + r)*DDIM + ss*128 + kc*16);
    }
    asm volatile("cp.async.commit_group;\n");

    auto loadB = [&](int s, int buf) {
        const int nc = colBase + (s >> 2), sc = s & 3;
        #pragma unroll
        for (int q = 0; q < 4; q++) {
            const int u = tid + 256*q;
            const int r = u >> 3, kc = u & 7;
            cp_cg16(sb + (uint32_t)(OFF_B + buf*SLICE_B + r*128 + ((kc*16) ^ ((r & 7) << 4))),
                    g_B8 + (size_t)(nc*128 + r)*DDIM + sc*128 + kc*16);
        }
        asm volatile("cp.async.commit_group;\n");
    };
    loadB(0, 0);
    loadB(1, 1);

    // ---- ldmatrix lane addresses ----
    const int grp = lane >> 3, wi = lane & 7;
    uint32_t aBase[4], aMask[4];
    const uint32_t aB16 = (uint32_t)((grp >> 1) * 16);
    #pragma unroll
    for (int mt = 0; mt < 4; mt++) {
        const int row = wm*64 + mt*16 + (grp & 1)*8 + wi;
        aBase[mt] = sb + (uint32_t)(row * 128);
        aMask[mt] = (uint32_t)((row & 7) << 4);
    }
    uint32_t bBase[2], bMask[2];
    const uint32_t bB16 = (uint32_t)((grp & 1) * 16);
    #pragma unroll
    for (int p = 0; p < 2; p++) {
        const int row = wn*32 + p*16 + (grp >> 1)*8 + wi;
        bBase[p] = sb + OFF_B + (uint32_t)(row * 128);
        bMask[p] = (uint32_t)((row & 7) << 4);
    }

    float rs[8];
    #pragma unroll
    for (int k = 0; k < 8; k++) rs[k] = 0.f;

    for (int c8 = 0; c8 < NCH_CTA; c8++) {
        uint32_t acc[4][4][2];
        #pragma unroll
        for (int x = 0; x < 4; x++)
            #pragma unroll
            for (int y = 0; y < 4; y++) { acc[x][y][0] = 0u; acc[x][y][1] = 0u; }

        #pragma unroll
        for (int sc = 0; sc < 4; sc++) {
            const int s = c8*4 + sc;
            if (s < NSLICE - 1) asm volatile("cp.async.wait_group 1;\n");
            else                asm volatile("cp.async.wait_group 0;\n");
            __syncthreads();
            // prefetch into buf (s+2)%3: last read at slice s-1, ordered by this barrier
            if (s + 2 < NSLICE) { int pb = s + 2 - ((s+2) >= 3 ? 3 : 0); pb = (s+2) % 3; loadB(s + 2, pb); }

            const uint32_t aSl = (uint32_t)(sc * SLICE_B);
            const uint32_t bBuf = (uint32_t)((s % 3) * SLICE_B);
            #pragma unroll
            for (int kk = 0; kk < 4; kk++) {
                uint32_t afr[4][4];
                #pragma unroll
                for (int mt = 0; mt < 4; mt++)
                    ldsm4(afr[mt], aBase[mt] + aSl + (((uint32_t)(kk*32) | aB16) ^ aMask[mt]));
                uint32_t bfr[4][2];
                #pragma unroll
                for (int p = 0; p < 2; p++) {
                    uint32_t t[4];
                    ldsm4(t, bBase[p] + bBuf + (((uint32_t)(kk*32) | bB16) ^ bMask[p]));
                    bfr[2*p][0] = t[0]; bfr[2*p][1] = t[1];
                    bfr[2*p+1][0] = t[2]; bfr[2*p+1][1] = t[3];
                }
                #pragma unroll
                for (int mt = 0; mt < 4; mt++)
                    #pragma unroll
                    for (int nt = 0; nt < 4; nt++)
                        mma_e4m3_h(acc[mt][nt], afr[mt], bfr[nt]);
            }
        }

        // epilogue: acc halves = K*cos ; f16 exp-sums, one f32 convert per pair
        #pragma unroll
        for (int mt = 0; mt < 4; mt++) {
            __half2 h0 = ex2_h2(__hmax2(*(__half2*)&acc[mt][0][0], cKh));
            __half2 h1 = ex2_h2(__hmax2(*(__half2*)&acc[mt][0][1], cKh));
            #pragma unroll
            for (int nt = 1; nt < 4; nt++) {
                h0 = __hadd2(h0, ex2_h2(__hmax2(*(__half2*)&acc[mt][nt][0], cKh)));
                h1 = __hadd2(h1, ex2_h2(__hmax2(*(__half2*)&acc[mt][nt][1], cKh)));
            }
            const float2 f0 = __half22float2(h0);
            const float2 f1 = __half22float2(h1);
            rs[mt*2]   += f0.x + f0.y;
            rs[mt*2+1] += f1.x + f1.y;
        }
    }

    // ---- row reduction into smem (overlay on B buffers; mainloop drained) ----
    __syncthreads();
    float* rowAcc = (float*)(dyns + OFF_B);
    if (tid < MT) rowAcc[tid] = 0.f;
    __syncthreads();

    const int g8 = lane >> 2, tt = lane & 3;
    #pragma unroll
    for (int k = 0; k < 8; k++) {
        float v = rs[k];
        v += __shfl_xor_sync(0xffffffffu, v, 1);
        v += __shfl_xor_sync(0xffffffffu, v, 2);
        if (tt == 0)
            atomicAdd(&rowAcc[wm*64 + (k >> 1)*16 + (k & 1)*8 + g8], v);
    }
    __syncthreads();

    if (tid < MT) atomicAdd(&g_rowsum[rowBase + tid], rowAcc[tid]);
    __threadfence();
    if (tid == 0) {
        const unsigned o = atomicAdd(&g_count[rowBlock], 1u);
        s_last = (o == 3u);
    }
    __syncthreads();

    // ---- last CTA of this row block computes the loss ----
    if (s_last) {
        __threadfence();
        float v = 0.f;
        if (tid < MT) {
            const int r = rowBase + tid;
            const float fF = g_cosF[r], fL = g_cosL[r];
            v = __logf(g_rowsum[r] - ex2f(K * fF) + ex2f(K * fL)) - w * fL;
        }
        #pragma unroll
        for (int o = 16; o; o >>= 1) v += __shfl_xor_sync(0xffffffffu, v, o);
        float* red = (float*)(dyns + OFF_B + 512);
        if (lane == 0) red[warp] = v;
        __syncthreads();
        if (tid == 0) {
            float t = 0.f;
            #pragma unroll
            for (int i = 0; i < 8; i++) t += red[i];
            atomicAdd(out, t);
        }
    }
}

// ---------------- launcher ----------------
extern "C" void kernel_launch(void* const* d_in, const int* in_sizes, int n_in,
                              void* d_out, int out_size) {
    const float* dvecs = (const float*)d_in[0];
    const float* wp    = (const float*)d_in[1];
    float* out = (float*)d_out;

    cudaFuncSetAttribute(k2_gemm, cudaFuncAttributeMaxDynamicSharedMemorySize, SMEM_K2);

    k1_prep<<<NSPK, 128>>>(dvecs, wp, out);
    k2_gemm<<<(NROWS/MT)*4, 256, SMEM_K2>>>(wp, out);
}